// round 1
// baseline (speedup 1.0000x reference)
#include <cuda_runtime.h>
#include <math.h>

#define NMAX 20000
#define EMAX 60000
#define EHMAX 30000
#define ML 128

// ---------------- scratch (static __device__ — no runtime alloc) ----------------
__device__ float g_buf[2][NMAX * ML];
__device__ float z_buf[2][EMAX * ML];
__device__ float agg_buf[NMAX * ML];
__device__ float dot_buf[EMAX];
__device__ float qhat_d[EMAX];
__device__ float qtilde_d[EMAX];
__device__ float qhatdir_d[EHMAX];
__device__ float loss_d[EMAX];
__device__ float dhat_d[NMAX];
__device__ float hbuf[2][NMAX];
__device__ int   knownbuf[2][NMAX];
__device__ float r_d[EMAX], pump_d[EMAX], c0_d[EMAX], c1_d[EMAX], c2_d[EMAX];
__device__ float hstar_d[NMAX], dstar_d[NMAX], resm_d[NMAX];
__device__ int   csr_off[NMAX], csr_cnt[NMAX], csr_cur[NMAX], csr_edge[EMAX];

// ---------------- setup kernels ----------------
__global__ void pack_kernel(const float* __restrict__ x, const float* __restrict__ ea,
                            int N, int E, int Eh) {
    int i = blockIdx.x * blockDim.x + threadIdx.x;
    if (i < E) {
        r_d[i]    = ea[i * 8 + 0];
        pump_d[i] = ea[i * 8 + 3];
        c0_d[i]   = ea[i * 8 + 4];
        c1_d[i]   = ea[i * 8 + 5];
        c2_d[i]   = ea[i * 8 + 6];
        qhat_d[i] = 0.f;
        qtilde_d[i] = 0.f;
        if (i < Eh) qhatdir_d[i] = 0.f;
    }
    if (i < N) {
        hstar_d[i] = x[i * 5 + 0];
        dstar_d[i] = x[i * 5 + 1];
        resm_d[i]  = x[i * 5 + 4];
        dhat_d[i]  = 0.f;
        csr_cnt[i] = 0;
    }
}

__global__ void csr_count_kernel(const int* __restrict__ rcvr, int E) {
    int e = blockIdx.x * blockDim.x + threadIdx.x;
    if (e < E) atomicAdd(&csr_cnt[rcvr[e]], 1);
}

__global__ void csr_scan_kernel(int N) {
    __shared__ int wsum[32];
    int t = threadIdx.x;
    int C = (N + 1023) >> 10;
    int beg = t * C;
    int end = beg + C; if (end > N) end = N;
    int s = 0;
    for (int i = beg; i < end; i++) s += csr_cnt[i];
    int lane = t & 31, w = t >> 5;
    int v = s;
    for (int o = 1; o < 32; o <<= 1) {
        int u = __shfl_up_sync(0xffffffffu, v, o);
        if (lane >= o) v += u;
    }
    if (lane == 31) wsum[w] = v;
    __syncthreads();
    if (w == 0) {
        int vv = wsum[lane];
        for (int o = 1; o < 32; o <<= 1) {
            int u = __shfl_up_sync(0xffffffffu, vv, o);
            if (lane >= o) vv += u;
        }
        wsum[lane] = vv;
    }
    __syncthreads();
    int base = (w > 0 ? wsum[w - 1] : 0) + (v - s);
    int run = base;
    for (int i = beg; i < end; i++) {
        csr_off[i] = run;
        csr_cur[i] = run;
        run += csr_cnt[i];
    }
}

__global__ void csr_fill_kernel(const int* __restrict__ rcvr, int E) {
    int e = blockIdx.x * blockDim.x + threadIdx.x;
    if (e < E) {
        int pos = atomicAdd(&csr_cur[rcvr[e]], 1);
        csr_edge[pos] = e;
    }
}

// ---------------- per-iteration init ----------------
__global__ void init_g_kernel(const float* __restrict__ Wni, int N) {
    int t = blockIdx.x * blockDim.x + threadIdx.x;
    if (t >= N * ML) return;
    int n = t >> 7, c = t & 127;
    g_buf[0][t] = dhat_d[n] * Wni[c] + dstar_d[n] * Wni[ML + c] + resm_d[n] * Wni[2 * ML + c];
}

__global__ void init_z_kernel(const float* __restrict__ We, int E) {
    int t = blockIdx.x * blockDim.x + threadIdx.x;
    if (t >= E * ML) return;
    int e = t >> 7, c = t & 127;
    z_buf[0][t] = qtilde_d[e] * We[c] + qhat_d[e] * We[ML + c];
}

// ---------------- GEMM constants ----------------
#define BM 64
#define BK 16
#define TM 8
#define TN 4

// edge MLP: z_new = relu([g[sndr], g[rcvr], z] @ W1) @ W2   (KDIM = 384)
__global__ __launch_bounds__(256) void edge_mlp_kernel(
    const float* __restrict__ W1, const float* __restrict__ W2,
    const int* __restrict__ sndr, const int* __restrict__ rcvr,
    int gp, int zp_in, int zp_out, int E) {
    __shared__ float As[BM][BK];
    __shared__ float Bs[BK][ML];
    __shared__ float Hs[BM][ML];
    __shared__ int srow[BM], rrow[BM];
    int tid = threadIdx.x;
    int row0 = blockIdx.x * BM;
    if (tid < BM) {
        int rr = row0 + tid;
        int cr = rr < E ? rr : E - 1;
        srow[tid] = sndr[cr];
        rrow[tid] = rcvr[cr];
    }
    __syncthreads();
    const float* g = g_buf[gp];
    const float* zin = z_buf[zp_in];
    float acc[TM][TN];
#pragma unroll
    for (int i = 0; i < TM; i++)
#pragma unroll
        for (int j = 0; j < TN; j++) acc[i][j] = 0.f;
    int wrow = tid >> 5, lane = tid & 31;
    int lm = tid >> 2, lk = (tid & 3) * 4;
    int bk = tid >> 4, bc = (tid & 15) * 8;
    for (int kb = 0; kb < 384; kb += BK) {
        __syncthreads();
        const float* asrc;
        if (kb < 128) asrc = g + (size_t)srow[lm] * ML + kb;
        else if (kb < 256) asrc = g + (size_t)rrow[lm] * ML + (kb - 128);
        else {
            int er = row0 + lm; if (er >= E) er = E - 1;
            asrc = zin + (size_t)er * ML + (kb - 256);
        }
        *(float4*)&As[lm][lk] = *(const float4*)(asrc + lk);
        const float* bsrc = W1 + (size_t)(kb + bk) * ML + bc;
        *(float4*)&Bs[bk][bc]     = *(const float4*)bsrc;
        *(float4*)&Bs[bk][bc + 4] = *(const float4*)(bsrc + 4);
        __syncthreads();
#pragma unroll
        for (int k = 0; k < BK; k++) {
            float a[TM];
#pragma unroll
            for (int i = 0; i < TM; i++) a[i] = As[wrow * TM + i][k];
            float4 bv = *(float4*)&Bs[k][lane * TN];
            float b[4] = {bv.x, bv.y, bv.z, bv.w};
#pragma unroll
            for (int i = 0; i < TM; i++)
#pragma unroll
                for (int j = 0; j < TN; j++) acc[i][j] = fmaf(a[i], b[j], acc[i][j]);
        }
    }
#pragma unroll
    for (int i = 0; i < TM; i++) {
        float4 hv;
        hv.x = fmaxf(acc[i][0], 0.f); hv.y = fmaxf(acc[i][1], 0.f);
        hv.z = fmaxf(acc[i][2], 0.f); hv.w = fmaxf(acc[i][3], 0.f);
        *(float4*)&Hs[wrow * TM + i][lane * TN] = hv;
        acc[i][0] = acc[i][1] = acc[i][2] = acc[i][3] = 0.f;
    }
    for (int kb = 0; kb < 128; kb += BK) {
        __syncthreads();
        const float* bsrc = W2 + (size_t)(kb + bk) * ML + bc;
        *(float4*)&Bs[bk][bc]     = *(const float4*)bsrc;
        *(float4*)&Bs[bk][bc + 4] = *(const float4*)(bsrc + 4);
        __syncthreads();
#pragma unroll
        for (int k = 0; k < BK; k++) {
            float a[TM];
#pragma unroll
            for (int i = 0; i < TM; i++) a[i] = Hs[wrow * TM + i][kb + k];
            float4 bv = *(float4*)&Bs[k][lane * TN];
            float b[4] = {bv.x, bv.y, bv.z, bv.w};
#pragma unroll
            for (int i = 0; i < TM; i++)
#pragma unroll
                for (int j = 0; j < TN; j++) acc[i][j] = fmaf(a[i], b[j], acc[i][j]);
        }
    }
    float* zout = z_buf[zp_out];
#pragma unroll
    for (int i = 0; i < TM; i++) {
        int grow = row0 + wrow * TM + i;
        if (grow < E) {
            float4 ov = {acc[i][0], acc[i][1], acc[i][2], acc[i][3]};
            *(float4*)&zout[(size_t)grow * ML + lane * TN] = ov;
        }
    }
}

// node MLP: g_new = relu([g, agg] @ W1) @ W2   (KDIM = 256)
__global__ __launch_bounds__(256) void node_mlp_kernel(
    const float* __restrict__ W1, const float* __restrict__ W2,
    int gp_in, int gp_out, int N) {
    __shared__ float As[BM][BK];
    __shared__ float Bs[BK][ML];
    __shared__ float Hs[BM][ML];
    int tid = threadIdx.x;
    int row0 = blockIdx.x * BM;
    const float* g = g_buf[gp_in];
    float acc[TM][TN];
#pragma unroll
    for (int i = 0; i < TM; i++)
#pragma unroll
        for (int j = 0; j < TN; j++) acc[i][j] = 0.f;
    int wrow = tid >> 5, lane = tid & 31;
    int lm = tid >> 2, lk = (tid & 3) * 4;
    int bk = tid >> 4, bc = (tid & 15) * 8;
    for (int kb = 0; kb < 256; kb += BK) {
        __syncthreads();
        int er = row0 + lm; if (er >= N) er = N - 1;
        const float* asrc;
        if (kb < 128) asrc = g + (size_t)er * ML + kb;
        else          asrc = agg_buf + (size_t)er * ML + (kb - 128);
        *(float4*)&As[lm][lk] = *(const float4*)(asrc + lk);
        const float* bsrc = W1 + (size_t)(kb + bk) * ML + bc;
        *(float4*)&Bs[bk][bc]     = *(const float4*)bsrc;
        *(float4*)&Bs[bk][bc + 4] = *(const float4*)(bsrc + 4);
        __syncthreads();
#pragma unroll
        for (int k = 0; k < BK; k++) {
            float a[TM];
#pragma unroll
            for (int i = 0; i < TM; i++) a[i] = As[wrow * TM + i][k];
            float4 bv = *(float4*)&Bs[k][lane * TN];
            float b[4] = {bv.x, bv.y, bv.z, bv.w};
#pragma unroll
            for (int i = 0; i < TM; i++)
#pragma unroll
                for (int j = 0; j < TN; j++) acc[i][j] = fmaf(a[i], b[j], acc[i][j]);
        }
    }
#pragma unroll
    for (int i = 0; i < TM; i++) {
        float4 hv;
        hv.x = fmaxf(acc[i][0], 0.f); hv.y = fmaxf(acc[i][1], 0.f);
        hv.z = fmaxf(acc[i][2], 0.f); hv.w = fmaxf(acc[i][3], 0.f);
        *(float4*)&Hs[wrow * TM + i][lane * TN] = hv;
        acc[i][0] = acc[i][1] = acc[i][2] = acc[i][3] = 0.f;
    }
    for (int kb = 0; kb < 128; kb += BK) {
        __syncthreads();
        const float* bsrc = W2 + (size_t)(kb + bk) * ML + bc;
        *(float4*)&Bs[bk][bc]     = *(const float4*)bsrc;
        *(float4*)&Bs[bk][bc + 4] = *(const float4*)(bsrc + 4);
        __syncthreads();
#pragma unroll
        for (int k = 0; k < BK; k++) {
            float a[TM];
#pragma unroll
            for (int i = 0; i < TM; i++) a[i] = Hs[wrow * TM + i][kb + k];
            float4 bv = *(float4*)&Bs[k][lane * TN];
            float b[4] = {bv.x, bv.y, bv.z, bv.w};
#pragma unroll
            for (int i = 0; i < TM; i++)
#pragma unroll
                for (int j = 0; j < TN; j++) acc[i][j] = fmaf(a[i], b[j], acc[i][j]);
        }
    }
    float* gout = g_buf[gp_out];
#pragma unroll
    for (int i = 0; i < TM; i++) {
        int grow = row0 + wrow * TM + i;
        if (grow < N) {
            float4 ov = {acc[i][0], acc[i][1], acc[i][2], acc[i][3]};
            *(float4*)&gout[(size_t)grow * ML + lane * TN] = ov;
        }
    }
}

// z_bar = [g[sndr], g[rcvr], z] @ Wz, then per-row dot with the proper half of Wf
__global__ __launch_bounds__(256) void zbar_kernel(
    const float* __restrict__ Wz, const float* __restrict__ Wf,
    const int* __restrict__ sndr, const int* __restrict__ rcvr,
    int gp, int zp, int E, int Eh) {
    __shared__ float As[BM][BK];
    __shared__ float Bs[BK][ML];
    __shared__ float wfs[256];
    __shared__ int srow[BM], rrow[BM];
    int tid = threadIdx.x;
    int row0 = blockIdx.x * BM;
    if (tid < 256) wfs[tid] = Wf[tid];
    if (tid < BM) {
        int rr = row0 + tid;
        int cr = rr < E ? rr : E - 1;
        srow[tid] = sndr[cr];
        rrow[tid] = rcvr[cr];
    }
    __syncthreads();
    const float* g = g_buf[gp];
    const float* zin = z_buf[zp];
    float acc[TM][TN];
#pragma unroll
    for (int i = 0; i < TM; i++)
#pragma unroll
        for (int j = 0; j < TN; j++) acc[i][j] = 0.f;
    int wrow = tid >> 5, lane = tid & 31;
    int lm = tid >> 2, lk = (tid & 3) * 4;
    int bk = tid >> 4, bc = (tid & 15) * 8;
    for (int kb = 0; kb < 384; kb += BK) {
        __syncthreads();
        const float* asrc;
        if (kb < 128) asrc = g + (size_t)srow[lm] * ML + kb;
        else if (kb < 256) asrc = g + (size_t)rrow[lm] * ML + (kb - 128);
        else {
            int er = row0 + lm; if (er >= E) er = E - 1;
            asrc = zin + (size_t)er * ML + (kb - 256);
        }
        *(float4*)&As[lm][lk] = *(const float4*)(asrc + lk);
        const float* bsrc = Wz + (size_t)(kb + bk) * ML + bc;
        *(float4*)&Bs[bk][bc]     = *(const float4*)bsrc;
        *(float4*)&Bs[bk][bc + 4] = *(const float4*)(bsrc + 4);
        __syncthreads();
#pragma unroll
        for (int k = 0; k < BK; k++) {
            float a[TM];
#pragma unroll
            for (int i = 0; i < TM; i++) a[i] = As[wrow * TM + i][k];
            float4 bv = *(float4*)&Bs[k][lane * TN];
            float b[4] = {bv.x, bv.y, bv.z, bv.w};
#pragma unroll
            for (int i = 0; i < TM; i++)
#pragma unroll
                for (int j = 0; j < TN; j++) acc[i][j] = fmaf(a[i], b[j], acc[i][j]);
        }
    }
#pragma unroll
    for (int i = 0; i < TM; i++) {
        int grow = row0 + wrow * TM + i;
        int off = (grow < Eh) ? 0 : 128;
        float p = acc[i][0] * wfs[off + lane * TN + 0]
                + acc[i][1] * wfs[off + lane * TN + 1]
                + acc[i][2] * wfs[off + lane * TN + 2]
                + acc[i][3] * wfs[off + lane * TN + 3];
#pragma unroll
        for (int o = 16; o; o >>= 1) p += __shfl_xor_sync(0xffffffffu, p, o);
        if (lane == 0 && grow < E) dot_buf[grow] = p;
    }
}

// ---------------- elementwise / graph kernels ----------------
__global__ void agg_kernel(int zp, int N) {
    int t = blockIdx.x * blockDim.x + threadIdx.x;
    if (t >= N * ML) return;
    int n = t >> 7, c = t & 127;
    const float* zn = z_buf[zp];
    int off = csr_off[n], cnt = csr_cnt[n];
    float m = -3.0e38f;
    for (int i = 0; i < cnt; i++)
        m = fmaxf(m, zn[(size_t)csr_edge[off + i] * ML + c]);
    agg_buf[t] = (cnt > 0) ? m : 0.f;
}

__global__ void update_qhat_kernel(int Eh) {
    int i = blockIdx.x * blockDim.x + threadIdx.x;
    if (i >= Eh) return;
    float qd = qhatdir_d[i] + dot_buf[i] + dot_buf[i + Eh];
    float pd = pump_d[Eh + i];
    if (pd == 1.0f) qd = fminf(qd, 0.f);
    if (pd == 2.0f) qd = 0.f;
    qhatdir_d[i] = qd;
    qhat_d[i] = qd;
    qhat_d[i + Eh] = -qd;
}

__global__ void edge_loss_kernel(int E) {
    int e = blockIdx.x * blockDim.x + threadIdx.x;
    if (e >= E) return;
    float q = qhat_d[e];
    float q2 = q * q + 1e-24f;
    float lp = r_d[e] * q * powf(q2, 0.426f);
    float lpu = -(c0_d[e] - c1_d[e] * powf(q2, c2_d[e] * 0.5f));
    loss_d[e] = (pump_d[e] != 0.f) ? lpu : lp;
}

__global__ void head_init_kernel(int N) {
    int n = blockIdx.x * blockDim.x + threadIdx.x;
    if (n >= N) return;
    int kn = resm_d[n] > 0.5f;
    hbuf[0][n] = kn ? hstar_d[n] : 0.f;
    knownbuf[0][n] = kn;
}

__global__ void head_prop_kernel(const int* __restrict__ sndr, int p, int N) {
    int n = blockIdx.x * blockDim.x + threadIdx.x;
    if (n >= N) return;
    const float* h = hbuf[p];
    const int* kn = knownbuf[p];
    int off = csr_off[n], cnt = csr_cnt[n];
    float m = -3.0e38f;
    for (int i = 0; i < cnt; i++) {
        int e = csr_edge[off + i];
        int s = sndr[e];
        if (kn[s]) m = fmaxf(m, h[s] - loss_d[e]);
    }
    int k0 = kn[n];
    float hv = h[n];
    if (!k0 && m > -5.0e8f) { hv = m; k0 = 1; }
    hbuf[1 - p][n] = hv;
    knownbuf[1 - p][n] = k0;
}

__global__ void qtilde_kernel(const int* __restrict__ sndr, const int* __restrict__ rcvr, int E) {
    int e = blockIdx.x * blockDim.x + threadIdx.x;
    if (e >= E) return;
    float dh = hbuf[0][sndr[e]] - hbuf[0][rcvr[e]];
    float q = dh * powf(dh * dh + 1e-24f, -0.23f) / powf(r_d[e], 0.54f);
    float pe = pump_d[e];
    if (pe != 0.f) q = 0.f;
    qtilde_d[e] = q;
    if (fabsf(pe) == 1.0f) qhat_d[e] = q;
}

__global__ void dhat_kernel(int N) {
    int n = blockIdx.x * blockDim.x + threadIdx.x;
    if (n >= N) return;
    int off = csr_off[n], cnt = csr_cnt[n];
    float s = 0.f;
    for (int i = 0; i < cnt; i++) s += qhat_d[csr_edge[off + i]];
    dhat_d[n] = s;
}

__global__ void out_kernel(float* __restrict__ out, int N) {
    int n = blockIdx.x * blockDim.x + threadIdx.x;
    if (n < N) out[n] = hbuf[0][n];
}

// ---------------- launch ----------------
extern "C" void kernel_launch(void* const* d_in, const int* in_sizes, int n_in,
                              void* d_out, int out_size) {
    const float* x     = (const float*)d_in[0];
    const float* ea    = (const float*)d_in[1];
    const float* Wni   = (const float*)d_in[2];
    const float* Wedge = (const float*)d_in[3];
    const float* Wz    = (const float*)d_in[4];
    const float* Wf    = (const float*)d_in[5];
    const float* We1   = (const float*)d_in[6];
    const float* We2   = (const float*)d_in[7];
    const float* Wn1   = (const float*)d_in[8];
    const float* Wn2   = (const float*)d_in[9];
    const int*   ei    = (const int*)d_in[10];

    int N  = in_sizes[0] / 5;
    int E  = in_sizes[10] / 2;
    int Eh = E / 2;
    const int* sndr = ei;
    const int* rcvr = ei + E;
    const int K = 3;  // r_iter=1 + n_iter=2 (fixed by dataset; device scalars unreadable under capture)
    const int TB = 256;
    int mNE = N > E ? N : E;

    pack_kernel<<<(mNE + TB - 1) / TB, TB>>>(x, ea, N, E, Eh);
    csr_count_kernel<<<(E + TB - 1) / TB, TB>>>(rcvr, E);
    csr_scan_kernel<<<1, 1024>>>(N);
    csr_fill_kernel<<<(E + TB - 1) / TB, TB>>>(rcvr, E);

    int gE = (E + BM - 1) / BM;
    int gN = (N + BM - 1) / BM;

    for (int k = 0; k < K; k++) {
        init_g_kernel<<<(N * ML + TB - 1) / TB, TB>>>(Wni, N);
        init_z_kernel<<<(E * ML + TB - 1) / TB, TB>>>(Wedge, E);
        int gp = 0, zp = 0;
        for (int i = 0; i < 2; i++) {
            edge_mlp_kernel<<<gE, 256>>>(We1 + (size_t)i * 384 * ML,
                                         We2 + (size_t)i * ML * ML,
                                         sndr, rcvr, gp, zp, 1 - zp, E);
            agg_kernel<<<(N * ML + TB - 1) / TB, TB>>>(1 - zp, N);
            node_mlp_kernel<<<gN, 256>>>(Wn1 + (size_t)i * 256 * ML,
                                         Wn2 + (size_t)i * ML * ML,
                                         gp, 1 - gp, N);
            gp = 1 - gp;
            zp = 1 - zp;
        }
        zbar_kernel<<<gE, 256>>>(Wz, Wf, sndr, rcvr, gp, zp, E, Eh);
        update_qhat_kernel<<<(Eh + TB - 1) / TB, TB>>>(Eh);
        edge_loss_kernel<<<(E + TB - 1) / TB, TB>>>(E);
        head_init_kernel<<<(N + TB - 1) / TB, TB>>>(N);
        for (int t = 0; t < 20; t++)
            head_prop_kernel<<<(N + TB - 1) / TB, TB>>>(sndr, t & 1, N);
        if (k < K - 1) {
            qtilde_kernel<<<(E + TB - 1) / TB, TB>>>(sndr, rcvr, E);
            dhat_kernel<<<(N + TB - 1) / TB, TB>>>(N);
        }
    }
    out_kernel<<<(N + TB - 1) / TB, TB>>>((float*)d_out, N);
}